// round 1
// baseline (speedup 1.0000x reference)
#include <cuda_runtime.h>
#include <cuda_bf16.h>

// Problem constants (fixed by setup_inputs)
constexpr int N  = 8;
constexpr int C  = 256;
constexpr int H  = 160;
constexpr int W  = 160;
constexpr int OH = 14;
constexpr int OW = 14;
constexpr float SCALE_H = 160.0f;
constexpr float SCALE_W = 160.0f;
constexpr int HW = H * W;          // 25600

// NHWC scratch: 8*160*160*256 floats = 200 MB (static __device__ — allowed)
__device__ float g_featT[(size_t)N * H * W * C];

// ---------------------------------------------------------------------------
// Kernel 1: NCHW -> NHWC transpose (per n: [C, HW] -> [HW, C]), 32x32 tiles
// ---------------------------------------------------------------------------
__global__ void nchw_to_nhwc_kernel(const float* __restrict__ feat) {
    __shared__ float tile[32][33];
    const int n   = blockIdx.z;
    const int hw0 = blockIdx.x * 32;
    const int c0  = blockIdx.y * 32;

    const float* src = feat + (size_t)n * C * HW;
    #pragma unroll
    for (int i = threadIdx.y; i < 32; i += 8) {
        tile[i][threadIdx.x] = src[(size_t)(c0 + i) * HW + hw0 + threadIdx.x];
    }
    __syncthreads();
    float* dst = g_featT + (size_t)n * HW * C;
    #pragma unroll
    for (int i = threadIdx.y; i < 32; i += 8) {
        dst[(size_t)(hw0 + i) * C + c0 + threadIdx.x] = tile[threadIdx.x][i];
    }
}

// ---------------------------------------------------------------------------
// Kernel 2: RoI Align. One block per (roi k, output row oy); 256 threads = C.
// Corner gathers are coalesced (consecutive channels contiguous in NHWC).
// Output staged in smem, flushed linearized for contiguous 14-float runs.
// ---------------------------------------------------------------------------
__global__ __launch_bounds__(256)
void roialign_kernel(const float* __restrict__ rois, float* __restrict__ out) {
    const int k  = blockIdx.x;
    const int oy = blockIdx.y;
    const int c  = threadIdx.x;

    __shared__ float s_roi[5];
    __shared__ int   s_x0[OW], s_x1[OW];
    __shared__ float s_w00[OW], s_w01[OW], s_w10[OW], s_w11[OW];
    __shared__ int   s_row0, s_row1;
    __shared__ float s_tile[C][OW + 1];

    if (threadIdx.x < 5) s_roi[threadIdx.x] = rois[k * 5 + threadIdx.x];
    __syncthreads();

    if (threadIdx.x < OW) {
        const int ox = threadIdx.x;
        const float px1 = s_roi[1] * SCALE_W;
        const float py1 = s_roi[2] * SCALE_H;
        const float px2 = s_roi[3] * SCALE_W;
        const float py2 = s_roi[4] * SCALE_H;

        const float gx = (float)ox * (1.0f / (float)(OW - 1));
        const float gy = (float)oy * (1.0f / (float)(OH - 1));
        const float fx = px1 + gx * (px2 - px1);
        const float fy = py1 + gy * (py2 - py1);

        // mirror the reference's (unaligned) coordinate math exactly
        const float ngx = fx / (float)W * 2.0f - 1.0f;
        const float ngy = fy / (float)H * 2.0f - 1.0f;
        const float ix  = ((ngx + 1.0f) * (float)W - 1.0f) * 0.5f;
        const float iy  = ((ngy + 1.0f) * (float)H - 1.0f) * 0.5f;

        const int x0  = (int)floorf(ix);
        const int y0  = (int)floorf(iy);
        const int x1i = x0 + 1;
        const int y1i = y0 + 1;

        const float wx1 = ix - (float)x0;
        const float wx0 = 1.0f - wx1;
        const float wy1 = iy - (float)y0;
        const float wy0 = 1.0f - wy1;

        const float vx0 = (x0  >= 0 && x0  < W) ? 1.0f : 0.0f;
        const float vx1 = (x1i >= 0 && x1i < W) ? 1.0f : 0.0f;
        const float vy0 = (y0  >= 0 && y0  < H) ? 1.0f : 0.0f;
        const float vy1 = (y1i >= 0 && y1i < H) ? 1.0f : 0.0f;

        const int x0c = min(max(x0,  0), W - 1);
        const int x1c = min(max(x1i, 0), W - 1);

        s_x0[ox]  = x0c * C;          // element offset along the x axis in NHWC
        s_x1[ox]  = x1c * C;
        s_w00[ox] = wy0 * wx0 * vy0 * vx0;
        s_w01[ox] = wy0 * wx1 * vy0 * vx1;
        s_w10[ox] = wy1 * wx0 * vy1 * vx0;
        s_w11[ox] = wy1 * wx1 * vy1 * vx1;

        if (ox == 0) {
            const int b   = (int)s_roi[0];
            const int y0c = min(max(y0,  0), H - 1);
            const int y1c = min(max(y1i, 0), H - 1);
            s_row0 = ((b * H + y0c) * W) * C;
            s_row1 = ((b * H + y1c) * W) * C;
        }
    }
    __syncthreads();

    const float* __restrict__ r0 = g_featT + s_row0 + c;
    const float* __restrict__ r1 = g_featT + s_row1 + c;

    #pragma unroll
    for (int ox = 0; ox < OW; ox++) {
        const int xo0 = s_x0[ox];
        const int xo1 = s_x1[ox];
        const float v00 = r0[xo0];
        const float v01 = r0[xo1];
        const float v10 = r1[xo0];
        const float v11 = r1[xo1];
        s_tile[c][ox] = v00 * s_w00[ox] + v01 * s_w01[ox]
                      + v10 * s_w10[ox] + v11 * s_w11[ox];
    }
    __syncthreads();

    // Linearized flush: consecutive lanes cover contiguous ox runs per channel
    float* __restrict__ outk = out + (size_t)k * C * OH * OW + oy * OW;
    constexpr int TOTAL = C * OW;     // 3584
    for (int j = threadIdx.x; j < TOTAL; j += 256) {
        const int cc = j / OW;
        const int ox = j - cc * OW;
        outk[cc * (OH * OW) + ox] = s_tile[cc][ox];
    }
}

extern "C" void kernel_launch(void* const* d_in, const int* in_sizes, int n_in,
                              void* d_out, int out_size) {
    const float* feat = (const float*)d_in[0];
    const float* rois = (const float*)d_in[1];
    float* out = (float*)d_out;

    const int K = in_sizes[1] / 5;   // 1024

    // Kernel 1: layout transform NCHW -> NHWC
    dim3 tgrid(HW / 32, C / 32, N);  // (800, 8, 8)
    dim3 tblock(32, 8);
    nchw_to_nhwc_kernel<<<tgrid, tblock>>>(feat);

    // Kernel 2: RoI align
    dim3 rgrid(K, OH);
    roialign_kernel<<<rgrid, 256>>>(rois, out);
}

// round 3
// speedup vs baseline: 1.7215x; 1.7215x over previous
#include <cuda_runtime.h>
#include <cuda_bf16.h>

// Problem constants (fixed by setup_inputs)
constexpr int N  = 8;
constexpr int C  = 256;
constexpr int H  = 160;
constexpr int W  = 160;
constexpr int OH = 14;
constexpr int OW = 14;
constexpr float SCALE_H = 160.0f;
constexpr float SCALE_W = 160.0f;
constexpr int HW = H * W;          // 25600
constexpr int C4 = C / 4;          // 64

// NHWC scratch: 8*160*160*256 floats = 200 MB (static __device__ — allowed)
__device__ float g_featT[(size_t)N * H * W * C];
// batch-sorted roi processing order
__device__ int   g_order[2048];

// ---------------------------------------------------------------------------
// Kernel 0: counting-sort roi indices by batch id (locality for L2 reuse).
// Single block. Order within a batch is nondeterministic but each roialign
// block writes only its own out[k] slice, so d_out is fully deterministic.
// ---------------------------------------------------------------------------
__global__ void sort_rois_kernel(const float* __restrict__ rois, int K) {
    __shared__ int cnt[N];
    __shared__ int base[N];
    const int t = threadIdx.x;
    if (t < N) cnt[t] = 0;
    __syncthreads();
    int b = 0;
    if (t < K) {
        b = (int)rois[t * 5];
        atomicAdd(&cnt[b], 1);
    }
    __syncthreads();
    if (t == 0) {
        int s = 0;
        for (int i = 0; i < N; i++) { base[i] = s; s += cnt[i]; }
    }
    __syncthreads();
    if (t < K) {
        int pos = atomicAdd(&base[b], 1);
        g_order[pos] = t;
    }
}

// ---------------------------------------------------------------------------
// Kernel 1: NCHW -> NHWC transpose, fully float4 both sides.
// 32(c) x 32(hw) float tile, block (8,32): 1 vec load + 1 vec store/thread.
// smem pitch 33 -> both phases bank-conflict-free.
// ---------------------------------------------------------------------------
__global__ __launch_bounds__(256)
void nchw_to_nhwc_kernel(const float* __restrict__ feat) {
    __shared__ float s[32][33];
    const int n   = blockIdx.z;
    const int hw0 = blockIdx.x * 32;
    const int c0  = blockIdx.y * 32;
    const int tx  = threadIdx.x;   // 0..7  (float4 lane)
    const int ty  = threadIdx.y;   // 0..31

    const float4* src4 = (const float4*)(feat + (size_t)n * C * HW);
    float4 v = src4[(size_t)(c0 + ty) * (HW / 4) + (hw0 >> 2) + tx];
    s[ty][tx * 4 + 0] = v.x;
    s[ty][tx * 4 + 1] = v.y;
    s[ty][tx * 4 + 2] = v.z;
    s[ty][tx * 4 + 3] = v.w;
    __syncthreads();

    float4 w;
    w.x = s[tx * 4 + 0][ty];
    w.y = s[tx * 4 + 1][ty];
    w.z = s[tx * 4 + 2][ty];
    w.w = s[tx * 4 + 3][ty];
    float4* dst4 = (float4*)(g_featT + (size_t)n * HW * C);
    dst4[(size_t)(hw0 + ty) * C4 + (c0 >> 2) + tx] = w;
}

// ---------------------------------------------------------------------------
// Kernel 2: RoI Align. 1-D grid of K*OH blocks, batch-major order so
// consecutive block IDs share one 26 MB image (fits in L2).
// 256 threads = 64 channel-quads x 4 ox-groups. All corner gathers are
// 128-bit, warp = 512B contiguous. Results staged in smem (float4 stores,
// conflict-free), flushed linearized for contiguous per-channel runs.
// ---------------------------------------------------------------------------
__global__ __launch_bounds__(256)
void roialign_kernel(const float* __restrict__ rois, float* __restrict__ out) {
    const int bid = blockIdx.x;
    const int oy  = bid % OH;
    const int tid = threadIdx.x;
    const int c4  = tid & 63;      // channel quad 0..63
    const int oxg = tid >> 6;      // ox group 0..3

    __shared__ int   s_k;
    __shared__ float s_roi[5];
    __shared__ int   s_o0[OW], s_o1[OW];
    __shared__ float s_w00[OW], s_w01[OW], s_w10[OW], s_w11[OW];
    __shared__ int   s_row0, s_row1;
    __shared__ float4 s_tile4[OW][C4 + 1];   // [ox][c4], pitch 65 float4

    if (tid == 0) s_k = g_order[bid / OH];
    __syncthreads();
    const int k = s_k;
    if (tid < 5) s_roi[tid] = rois[k * 5 + tid];
    __syncthreads();

    if (tid < OW) {
        const int ox = tid;
        const float px1 = s_roi[1] * SCALE_W;
        const float py1 = s_roi[2] * SCALE_H;
        const float px2 = s_roi[3] * SCALE_W;
        const float py2 = s_roi[4] * SCALE_H;

        const float gx = (float)ox * (1.0f / (float)(OW - 1));
        const float gy = (float)oy * (1.0f / (float)(OH - 1));
        const float fx = px1 + gx * (px2 - px1);
        const float fy = py1 + gy * (py2 - py1);

        // mirror the reference's (unaligned) coordinate math exactly
        const float ngx = fx / (float)W * 2.0f - 1.0f;
        const float ngy = fy / (float)H * 2.0f - 1.0f;
        const float ix  = ((ngx + 1.0f) * (float)W - 1.0f) * 0.5f;
        const float iy  = ((ngy + 1.0f) * (float)H - 1.0f) * 0.5f;

        const int x0  = (int)floorf(ix);
        const int y0  = (int)floorf(iy);
        const int x1i = x0 + 1;
        const int y1i = y0 + 1;

        const float wx1 = ix - (float)x0;
        const float wx0 = 1.0f - wx1;
        const float wy1 = iy - (float)y0;
        const float wy0 = 1.0f - wy1;

        const float vx0 = (x0  >= 0 && x0  < W) ? 1.0f : 0.0f;
        const float vx1 = (x1i >= 0 && x1i < W) ? 1.0f : 0.0f;
        const float vy0 = (y0  >= 0 && y0  < H) ? 1.0f : 0.0f;
        const float vy1 = (y1i >= 0 && y1i < H) ? 1.0f : 0.0f;

        const int x0c = min(max(x0,  0), W - 1);
        const int x1c = min(max(x1i, 0), W - 1);

        s_o0[ox]  = x0c * C4;      // x offset in float4 units
        s_o1[ox]  = x1c * C4;
        s_w00[ox] = wy0 * wx0 * vy0 * vx0;
        s_w01[ox] = wy0 * wx1 * vy0 * vx1;
        s_w10[ox] = wy1 * wx0 * vy1 * vx0;
        s_w11[ox] = wy1 * wx1 * vy1 * vx1;

        if (ox == 0) {
            const int b   = (int)s_roi[0];
            const int y0c = min(max(y0,  0), H - 1);
            const int y1c = min(max(y1i, 0), H - 1);
            s_row0 = (b * H + y0c) * W * C4;   // row offset in float4 units
            s_row1 = (b * H + y1c) * W * C4;
        }
    }
    __syncthreads();

    const float4* __restrict__ f = (const float4*)g_featT;
    const int r0 = s_row0;
    const int r1 = s_row1;

    #pragma unroll
    for (int ox = oxg; ox < OW; ox += 4) {
        const int a0 = s_o0[ox] + c4;
        const int a1 = s_o1[ox] + c4;
        const float w00 = s_w00[ox];
        const float w01 = s_w01[ox];
        const float w10 = s_w10[ox];
        const float w11 = s_w11[ox];
        const float4 v00 = __ldg(&f[r0 + a0]);
        const float4 v01 = __ldg(&f[r0 + a1]);
        const float4 v10 = __ldg(&f[r1 + a0]);
        const float4 v11 = __ldg(&f[r1 + a1]);
        float4 r;
        r.x = v00.x * w00 + v01.x * w01 + v10.x * w10 + v11.x * w11;
        r.y = v00.y * w00 + v01.y * w01 + v10.y * w10 + v11.y * w11;
        r.z = v00.z * w00 + v01.z * w01 + v10.z * w10 + v11.z * w11;
        r.w = v00.w * w00 + v01.w * w01 + v10.w * w10 + v11.w * w11;
        s_tile4[ox][c4] = r;
    }
    __syncthreads();

    // Linearized flush: s_tile viewed as [ox][c] floats with pitch 260
    const float* s_t = (const float*)s_tile4;
    float* __restrict__ outk = out + (size_t)k * C * OH * OW + oy * OW;
    constexpr int TOTAL = C * OW;        // 3584
    constexpr int PITCH = (C4 + 1) * 4;  // 260
    for (int j = tid; j < TOTAL; j += 256) {
        const int cc = j / OW;
        const int ox = j - cc * OW;
        outk[cc * (OH * OW) + ox] = s_t[ox * PITCH + cc];
    }
}

extern "C" void kernel_launch(void* const* d_in, const int* in_sizes, int n_in,
                              void* d_out, int out_size) {
    const float* feat = (const float*)d_in[0];
    const float* rois = (const float*)d_in[1];
    float* out = (float*)d_out;

    const int K = in_sizes[1] / 5;   // 1024

    // Kernel 0: batch-sort roi order for L2 locality
    sort_rois_kernel<<<1, 1024>>>(rois, K);

    // Kernel 1: layout transform NCHW -> NHWC (vectorized)
    dim3 tgrid(HW / 32, C / 32, N);  // (800, 8, 8)
    dim3 tblock(8, 32);
    nchw_to_nhwc_kernel<<<tgrid, tblock>>>(feat);

    // Kernel 2: RoI align (1-D batch-major grid)
    roialign_kernel<<<K * OH, 256>>>(rois, out);
}